// round 12
// baseline (speedup 1.0000x reference)
#include <cuda_runtime.h>
#include <cstdint>

// CRF loss: inputs [1024,512,50] f32, transitions [50,50] f32,
// masks [1024,512] int32 (bool as i32), tag_indices [1024,512] i32.
// Output: [0] = loss scalar, [1..2500] = transitions passthrough.
// Strategy: fwd-bwd split (warp0 alpha / warp1 beta) x 2 batch rows per warp
// interleaved (ILP fills the serial-chain stalls). E table shared across rows.

#define BSZ 1024
#define SLEN 512
#define NC 50
#define LOG2E 1.4426950408889634f
#define LN2   0.6931471805599453f

typedef unsigned long long ull;

__device__ float g_partial[BSZ];
__device__ unsigned int g_count = 0;

__device__ __forceinline__ ull ffma2(ull a, ull b, ull c) {
    ull d;
    asm("fma.rn.f32x2 %0, %1, %2, %3;" : "=l"(d) : "l"(a), "l"(b), "l"(c));
    return d;
}
__device__ __forceinline__ ull fadd2(ull a, ull b) {
    ull d;
    asm("add.rn.f32x2 %0, %1, %2;" : "=l"(d) : "l"(a), "l"(b));
    return d;
}
__device__ __forceinline__ ull pack2(float lo, float hi) {
    ull d;
    asm("mov.b64 %0, {%1, %2};" : "=l"(d) : "f"(lo), "f"(hi));
    return d;
}
__device__ __forceinline__ void unpack2(float& lo, float& hi, ull v) {
    asm("mov.b64 {%0, %1}, %2;" : "=f"(lo), "=f"(hi) : "l"(v));
}
__device__ __forceinline__ float ex2f(float a) {
    float r; asm("ex2.approx.ftz.f32 %0, %1;" : "=f"(r) : "f"(a)); return r;
}
__device__ __forceinline__ float lg2f(float a) {
    float r; asm("lg2.approx.ftz.f32 %0, %1;" : "=f"(r) : "f"(a)); return r;
}

// Fused 2-row matvec: s{A,B}[c2], s{A,B}[c2+1] = sum_c1 v{A,B}[c1]*E[c1][..]
__device__ __forceinline__ void matvec50x2(
    const float2* __restrict__ bufA, const float2* __restrict__ bufB,
    const ull* __restrict__ E0, const ull* __restrict__ E1,
    float& sA0, float& sA1, float& sB0, float& sB1)
{
    const ull* pa = reinterpret_cast<const ull*>(bufA);
    const ull* pb = reinterpret_cast<const ull*>(bufB);
    ull aA0 = 0, aA1 = 0, bA0 = 0, bA1 = 0;
    ull aB0 = 0, aB1 = 0, bB0 = 0, bB1 = 0;
    #pragma unroll
    for (int i = 0; i < 24; i += 2) {
        ull vA0 = pa[i], vA1 = pa[i + 1];
        ull vB0 = pb[i], vB1 = pb[i + 1];
        aA0 = ffma2(vA0, E0[i],     aA0);
        bA0 = ffma2(vA0, E1[i],     bA0);
        aB0 = ffma2(vB0, E0[i],     aB0);
        bB0 = ffma2(vB0, E1[i],     bB0);
        aA1 = ffma2(vA1, E0[i + 1], aA1);
        bA1 = ffma2(vA1, E1[i + 1], bA1);
        aB1 = ffma2(vB1, E0[i + 1], aB1);
        bB1 = ffma2(vB1, E1[i + 1], bB1);
    }
    {
        ull vA = pa[24], vB = pb[24];
        aA0 = ffma2(vA, E0[24], aA0);
        bA0 = ffma2(vA, E1[24], bA0);
        aB0 = ffma2(vB, E0[24], aB0);
        bB0 = ffma2(vB, E1[24], bB0);
    }
    aA0 = fadd2(aA0, aA1); bA0 = fadd2(bA0, bA1);
    aB0 = fadd2(aB0, aB1); bB0 = fadd2(bB0, bB1);
    float u, v;
    unpack2(u, v, aA0); sA0 = u + v;
    unpack2(u, v, bA0); sA1 = u + v;
    unpack2(u, v, aB0); sB0 = u + v;
    unpack2(u, v, bB0); sB1 = u + v;
}

// Forward pair-step (log2 domain), predicated per row (padding freeze).
__device__ __forceinline__ void crf_fstep2(
    float2 xa, float2 xb, float2& bA, float2& bB, float& mA, float& mB,
    float2* __restrict__ bufA, float2* __restrict__ bufB,
    const ull* __restrict__ Ec0, const ull* __restrict__ Ec1,
    bool updA, bool updB, bool act, int lane)
{
    float pA0 = ex2f(bA.x - mA), pA1 = ex2f(bA.y - mA);
    float pB0 = ex2f(bB.x - mB), pB1 = ex2f(bB.y - mB);
    float mnA = __shfl_sync(0xffffffffu, bA.x, 0);  // stale shift, exact math
    float mnB = __shfl_sync(0xffffffffu, bB.x, 0);
    if (act) {
        bufA[lane] = make_float2(pA0, pA1);
        bufB[lane] = make_float2(pB0, pB1);
    }
    __syncwarp();
    float sA0, sA1, sB0, sB1;
    matvec50x2(bufA, bufB, Ec0, Ec1, sA0, sA1, sB0, sB1);
    if (act && updA) {
        bA.x = fmaf(xa.x, LOG2E, mA + lg2f(sA0));
        bA.y = fmaf(xa.y, LOG2E, mA + lg2f(sA1));
    }
    if (act && updB) {
        bB.x = fmaf(xb.x, LOG2E, mB + lg2f(sB0));
        bB.y = fmaf(xb.y, LOG2E, mB + lg2f(sB1));
    }
    mA = mnA; mB = mnB;
}

// Backward pair-step: bbeta = m + lg2(E * exp2(bx_{t+1}+bbeta - m))
__device__ __forceinline__ void crf_bstep2(
    float2 xa, float2 xb, float2& bA, float2& bB, float& mA, float& mB,
    float2* __restrict__ bufA, float2* __restrict__ bufB,
    const ull* __restrict__ Er0, const ull* __restrict__ Er1,
    bool updA, bool updB, bool act, int lane)
{
    float wA0 = fmaf(xa.x, LOG2E, bA.x);   // inactive: 0 + -inf = -inf
    float wA1 = fmaf(xa.y, LOG2E, bA.y);
    float wB0 = fmaf(xb.x, LOG2E, bB.x);
    float wB1 = fmaf(xb.y, LOG2E, bB.y);
    float vA0 = ex2f(wA0 - mA), vA1 = ex2f(wA1 - mA);
    float vB0 = ex2f(wB0 - mB), vB1 = ex2f(wB1 - mB);
    float mnA = __shfl_sync(0xffffffffu, wA0, 0);
    float mnB = __shfl_sync(0xffffffffu, wB0, 0);
    if (act) {
        bufA[lane] = make_float2(vA0, vA1);
        bufB[lane] = make_float2(vB0, vB1);
    }
    __syncwarp();
    float sA0, sA1, sB0, sB1;
    matvec50x2(bufA, bufB, Er0, Er1, sA0, sA1, sB0, sB1);
    if (act && updA) { bA.x = mA + lg2f(sA0); bA.y = mA + lg2f(sA1); }
    if (act && updB) { bB.x = mB + lg2f(sB0); bB.y = mB + lg2f(sB1); }
    mA = mnA; mB = mnB;
}

__global__ void __launch_bounds__(64) crf_fused_kernel(
    const float* __restrict__ x,      // [BSZ, SLEN, NC]
    const float* __restrict__ T,      // [NC, NC]
    const int* __restrict__ maskI,    // [BSZ, SLEN] int32 0/1
    const int* __restrict__ tags,     // [BSZ, SLEN]
    float* __restrict__ out, int out_size)
{
    __shared__ float sT[NC * NC];
    __shared__ float2 spf[2][2][26];  // [buf][row][lane] forward p
    __shared__ float2 spb[2][2][26];  // backward v
    __shared__ int stags[2][SLEN];
    __shared__ float salpha[2][52], sbeta[2][52];

    const int tid = threadIdx.x;
    const int wid = tid >> 5;         // 0 = forward warp, 1 = backward warp
    const int lane = tid & 31;
    const int bp = blockIdx.x;        // block handles rows 2bp, 2bp+1
    const int rA = 2 * bp, rB = 2 * bp + 1;
    const int c2 = 2 * lane;
    const bool act = (lane < 25);

    for (int i = tid; i < NC * NC; i += 64) sT[i] = T[i];

    // --- lengths of both rows (computed redundantly in each warp) ---
    int lenA, lenB;
    {
        const int4* ma = reinterpret_cast<const int4*>(maskI + (size_t)rA * SLEN);
        const int4* mb = reinterpret_cast<const int4*>(maskI + (size_t)rB * SLEN);
        int sa = 0, sb = 0;
        #pragma unroll
        for (int k = 0; k < 4; ++k) {
            int4 va = ma[lane + 32 * k];
            int4 vb = mb[lane + 32 * k];
            sa += va.x + va.y + va.z + va.w;
            sb += vb.x + vb.y + vb.z + vb.w;
        }
        #pragma unroll
        for (int o = 16; o; o >>= 1) {
            sa += __shfl_xor_sync(0xffffffffu, sa, o);
            sb += __shfl_xor_sync(0xffffffffu, sb, o);
        }
        lenA = SLEN - sa;             // monotone mask => in [128, 512]
        lenB = SLEN - sb;
    }
    const int midA = (lenA - 1) >> 1, midB = (lenB - 1) >> 1;

    // --- own-row tags + unary/binary (warp w owns row 2bp+w) ---
    const int myLen = wid ? lenB : lenA;
    const int myRow = 2 * bp + wid;
    const int* trow = tags + (size_t)myRow * SLEN;
    for (int i = lane; i < myLen; i += 32) stags[wid][i] = trow[i];
    __syncwarp();

    const float* xrowMy = x + (size_t)myRow * SLEN * NC;
    float ub = 0.f;
    for (int t = lane; t < myLen; t += 32) {
        int tg = stags[wid][t];
        ub += __ldg(xrowMy + (size_t)t * NC + tg);
        if (t > 0) ub += sT[stags[wid][t - 1] * NC + tg];
    }
    #pragma unroll
    for (int o = 16; o; o >>= 1)
        ub += __shfl_xor_sync(0xffffffffu, ub, o);

    const float* xrowA = x + (size_t)rA * SLEN * NC;
    const float* xrowB = x + (size_t)rB * SLEN * NC;

    if (wid == 0) {
        // ================= FORWARD both rows: t = 1..mid =================
        ull Ec0[25], Ec1[25];     // E columns c2, c2+1 (shared by rows)
        #pragma unroll
        for (int i = 0; i < 25; ++i) {
            float e00 = 0.f, e01 = 0.f, e10 = 0.f, e11 = 0.f;
            if (act) {
                e00 = ex2f(sT[(2 * i) * NC + c2] * LOG2E);
                e01 = ex2f(sT[(2 * i + 1) * NC + c2] * LOG2E);
                e10 = ex2f(sT[(2 * i) * NC + c2 + 1] * LOG2E);
                e11 = ex2f(sT[(2 * i + 1) * NC + c2 + 1] * LOG2E);
            }
            Ec0[i] = pack2(e00, e01);
            Ec1[i] = pack2(e10, e11);
        }

        float2 xa0 = act ? *reinterpret_cast<const float2*>(xrowA + c2)
                         : make_float2(0.f, 0.f);
        float2 xb0 = act ? *reinterpret_cast<const float2*>(xrowB + c2)
                         : make_float2(0.f, 0.f);
        float2 bAv = act ? make_float2(xa0.x * LOG2E, xa0.y * LOG2E)
                         : make_float2(-INFINITY, -INFINITY);
        float2 bBv = act ? make_float2(xb0.x * LOG2E, xb0.y * LOG2E)
                         : make_float2(-INFINITY, -INFINITY);
        float mA = __shfl_sync(0xffffffffu, bAv.x, 0);
        float mB = __shfl_sync(0xffffffffu, bBv.x, 0);

        const int lenFa = midA + 1, lenFb = midB + 1;   // >= 64
        const int maxF = max(lenFa, lenFb);             // <= 256 < SLEN

        float2 xa1, xa2, xa3, xa4, xb1, xb2, xb3, xb4;
        xa1 = xa2 = xa3 = xa4 = xb1 = xb2 = xb3 = xb4 = make_float2(0.f, 0.f);
        if (act) {
            xa1 = *reinterpret_cast<const float2*>(xrowA + 1 * NC + c2);
            xa2 = *reinterpret_cast<const float2*>(xrowA + 2 * NC + c2);
            xa3 = *reinterpret_cast<const float2*>(xrowA + 3 * NC + c2);
            xa4 = *reinterpret_cast<const float2*>(xrowA + 4 * NC + c2);
            xb1 = *reinterpret_cast<const float2*>(xrowB + 1 * NC + c2);
            xb2 = *reinterpret_cast<const float2*>(xrowB + 2 * NC + c2);
            xb3 = *reinterpret_cast<const float2*>(xrowB + 3 * NC + c2);
            xb4 = *reinterpret_cast<const float2*>(xrowB + 4 * NC + c2);
        }
        float2* bA0 = spf[0][0]; float2* bA1 = spf[1][0];
        float2* bB0 = spf[0][1]; float2* bB1 = spf[1][1];

        int t = 1;
        for (; t + 7 < maxF; t += 4) {
            // prefetch steps t+4..t+7 both rows (indices < maxF+3 < 512: safe)
            float2 na1, na2, na3, na4, nb1, nb2, nb3, nb4;
            na1 = na2 = na3 = na4 = nb1 = nb2 = nb3 = nb4 = make_float2(0.f, 0.f);
            if (act) {
                const float* pa = xrowA + (size_t)(t + 4) * NC + c2;
                const float* pb = xrowB + (size_t)(t + 4) * NC + c2;
                na1 = *reinterpret_cast<const float2*>(pa);
                nb1 = *reinterpret_cast<const float2*>(pb);
                na2 = *reinterpret_cast<const float2*>(pa + NC);
                nb2 = *reinterpret_cast<const float2*>(pb + NC);
                na3 = *reinterpret_cast<const float2*>(pa + 2 * NC);
                nb3 = *reinterpret_cast<const float2*>(pb + 2 * NC);
                na4 = *reinterpret_cast<const float2*>(pa + 3 * NC);
                nb4 = *reinterpret_cast<const float2*>(pb + 3 * NC);
            }
            crf_fstep2(xa1, xb1, bAv, bBv, mA, mB, bA0, bB0, Ec0, Ec1,
                       t < lenFa, t < lenFb, act, lane);
            crf_fstep2(xa2, xb2, bAv, bBv, mA, mB, bA1, bB1, Ec0, Ec1,
                       t + 1 < lenFa, t + 1 < lenFb, act, lane);
            crf_fstep2(xa3, xb3, bAv, bBv, mA, mB, bA0, bB0, Ec0, Ec1,
                       t + 2 < lenFa, t + 2 < lenFb, act, lane);
            crf_fstep2(xa4, xb4, bAv, bBv, mA, mB, bA1, bB1, Ec0, Ec1,
                       t + 3 < lenFa, t + 3 < lenFb, act, lane);
            xa1 = na1; xa2 = na2; xa3 = na3; xa4 = na4;
            xb1 = nb1; xb2 = nb2; xb3 = nb3; xb4 = nb4;
        }
        // epilogue: 4 <= maxF - t <= 7
        crf_fstep2(xa1, xb1, bAv, bBv, mA, mB, bA0, bB0, Ec0, Ec1,
                   t < lenFa, t < lenFb, act, lane);
        crf_fstep2(xa2, xb2, bAv, bBv, mA, mB, bA1, bB1, Ec0, Ec1,
                   t + 1 < lenFa, t + 1 < lenFb, act, lane);
        crf_fstep2(xa3, xb3, bAv, bBv, mA, mB, bA0, bB0, Ec0, Ec1,
                   t + 2 < lenFa, t + 2 < lenFb, act, lane);
        crf_fstep2(xa4, xb4, bAv, bBv, mA, mB, bA1, bB1, Ec0, Ec1,
                   t + 3 < lenFa, t + 3 < lenFb, act, lane);
        int parity = 0;
        for (int u = t + 4; u < maxF; ++u) {
            float2 da = make_float2(0.f, 0.f), db = da;
            if (act) {
                da = *reinterpret_cast<const float2*>(xrowA + (size_t)u * NC + c2);
                db = *reinterpret_cast<const float2*>(xrowB + (size_t)u * NC + c2);
            }
            crf_fstep2(da, db, bAv, bBv, mA, mB,
                       parity ? bA1 : bA0, parity ? bB1 : bB0, Ec0, Ec1,
                       u < lenFa, u < lenFb, act, lane);
            parity ^= 1;
        }
        if (act) {
            salpha[0][c2] = bAv.x; salpha[0][c2 + 1] = bAv.y;
            salpha[1][c2] = bBv.x; salpha[1][c2 + 1] = bBv.y;
        }
    } else {
        // ================= BACKWARD both rows =================
        ull Er0[25], Er1[25];     // E rows c2, c2+1
        #pragma unroll
        for (int i = 0; i < 25; ++i) {
            float e00 = 0.f, e01 = 0.f, e10 = 0.f, e11 = 0.f;
            if (act) {
                e00 = ex2f(sT[c2 * NC + 2 * i] * LOG2E);
                e01 = ex2f(sT[c2 * NC + 2 * i + 1] * LOG2E);
                e10 = ex2f(sT[(c2 + 1) * NC + 2 * i] * LOG2E);
                e11 = ex2f(sT[(c2 + 1) * NC + 2 * i + 1] * LOG2E);
            }
            Er0[i] = pack2(e00, e01);
            Er1[i] = pack2(e10, e11);
        }

        float2 bAv = act ? make_float2(0.f, 0.f)
                         : make_float2(-INFINITY, -INFINITY);
        float2 bBv = bAv;
        const int NBa = lenA - 1 - midA, NBb = lenB - 1 - midB;  // >= 63
        const int maxB = max(NBa, NBb);

        // j-th step consumes x[len-1-j]; clamp index at 0 for padded steps
        #define XLA(j) (xrowA + (size_t)max(lenA - 1 - (j), 0) * NC + c2)
        #define XLB(j) (xrowB + (size_t)max(lenB - 1 - (j), 0) * NC + c2)

        float2 xa1, xa2, xa3, xa4, xb1, xb2, xb3, xb4;
        xa1 = xa2 = xa3 = xa4 = xb1 = xb2 = xb3 = xb4 = make_float2(0.f, 0.f);
        if (act) {
            xa1 = *reinterpret_cast<const float2*>(XLA(0));
            xa2 = *reinterpret_cast<const float2*>(XLA(1));
            xa3 = *reinterpret_cast<const float2*>(XLA(2));
            xa4 = *reinterpret_cast<const float2*>(XLA(3));
            xb1 = *reinterpret_cast<const float2*>(XLB(0));
            xb2 = *reinterpret_cast<const float2*>(XLB(1));
            xb3 = *reinterpret_cast<const float2*>(XLB(2));
            xb4 = *reinterpret_cast<const float2*>(XLB(3));
        }
        // exact shift for first step: w[0] = bx_{len-1}[0] + 0
        float mA = __shfl_sync(0xffffffffu, xa1.x * LOG2E, 0);
        float mB = __shfl_sync(0xffffffffu, xb1.x * LOG2E, 0);

        float2* bA0 = spb[0][0]; float2* bA1 = spb[1][0];
        float2* bB0 = spb[0][1]; float2* bB1 = spb[1][1];

        int j = 0;
        for (; j + 7 < maxB; j += 4) {
            float2 na1, na2, na3, na4, nb1, nb2, nb3, nb4;
            na1 = na2 = na3 = na4 = nb1 = nb2 = nb3 = nb4 = make_float2(0.f, 0.f);
            if (act) {
                na1 = *reinterpret_cast<const float2*>(XLA(j + 4));
                nb1 = *reinterpret_cast<const float2*>(XLB(j + 4));
                na2 = *reinterpret_cast<const float2*>(XLA(j + 5));
                nb2 = *reinterpret_cast<const float2*>(XLB(j + 5));
                na3 = *reinterpret_cast<const float2*>(XLA(j + 6));
                nb3 = *reinterpret_cast<const float2*>(XLB(j + 6));
                na4 = *reinterpret_cast<const float2*>(XLA(j + 7));
                nb4 = *reinterpret_cast<const float2*>(XLB(j + 7));
            }
            crf_bstep2(xa1, xb1, bAv, bBv, mA, mB, bA0, bB0, Er0, Er1,
                       j < NBa, j < NBb, act, lane);
            crf_bstep2(xa2, xb2, bAv, bBv, mA, mB, bA1, bB1, Er0, Er1,
                       j + 1 < NBa, j + 1 < NBb, act, lane);
            crf_bstep2(xa3, xb3, bAv, bBv, mA, mB, bA0, bB0, Er0, Er1,
                       j + 2 < NBa, j + 2 < NBb, act, lane);
            crf_bstep2(xa4, xb4, bAv, bBv, mA, mB, bA1, bB1, Er0, Er1,
                       j + 3 < NBa, j + 3 < NBb, act, lane);
            xa1 = na1; xa2 = na2; xa3 = na3; xa4 = na4;
            xb1 = nb1; xb2 = nb2; xb3 = nb3; xb4 = nb4;
        }
        crf_bstep2(xa1, xb1, bAv, bBv, mA, mB, bA0, bB0, Er0, Er1,
                   j < NBa, j < NBb, act, lane);
        crf_bstep2(xa2, xb2, bAv, bBv, mA, mB, bA1, bB1, Er0, Er1,
                   j + 1 < NBa, j + 1 < NBb, act, lane);
        crf_bstep2(xa3, xb3, bAv, bBv, mA, mB, bA0, bB0, Er0, Er1,
                   j + 2 < NBa, j + 2 < NBb, act, lane);
        crf_bstep2(xa4, xb4, bAv, bBv, mA, mB, bA1, bB1, Er0, Er1,
                   j + 3 < NBa, j + 3 < NBb, act, lane);
        int parity = 0;
        for (int u = j + 4; u < maxB; ++u) {
            float2 da = make_float2(0.f, 0.f), db = da;
            if (act) {
                da = *reinterpret_cast<const float2*>(XLA(u));
                db = *reinterpret_cast<const float2*>(XLB(u));
            }
            crf_bstep2(da, db, bAv, bBv, mA, mB,
                       parity ? bA1 : bA0, parity ? bB1 : bB0, Er0, Er1,
                       u < NBa, u < NBb, act, lane);
            parity ^= 1;
        }
        #undef XLA
        #undef XLB
        if (act) {
            sbeta[0][c2] = bAv.x; sbeta[0][c2 + 1] = bAv.y;
            sbeta[1][c2] = bBv.x; sbeta[1][c2 + 1] = bBv.y;
        }
    }
    __syncthreads();

    // --- combine: warp w handles row 2bp+w ---
    {
        float g0 = act ? salpha[wid][c2] + sbeta[wid][c2] : -INFINITY;
        float g1 = act ? salpha[wid][c2 + 1] + sbeta[wid][c2 + 1] : -INFINITY;
        float mx = fmaxf(g0, g1);
        #pragma unroll
        for (int o = 16; o; o >>= 1)
            mx = fmaxf(mx, __shfl_xor_sync(0xffffffffu, mx, o));
        float es = ex2f(g0 - mx) + ex2f(g1 - mx);
        #pragma unroll
        for (int o = 16; o; o >>= 1)
            es += __shfl_xor_sync(0xffffffffu, es, o);
        float log_norm = LN2 * (mx + lg2f(es));
        if (lane == 0) g_partial[myRow] = ub - log_norm;
    }

    // --- fused finalize: last block reduces and writes output ---
    __threadfence();
    __syncthreads();
    if (wid == 0) {
        unsigned int ticket = 0;
        if (lane == 0) ticket = atomicAdd(&g_count, 1u);
        ticket = __shfl_sync(0xffffffffu, ticket, 0);
        if (ticket == (BSZ / 2) - 1) {
            __threadfence();
            float s = 0.f;
            for (int i = lane; i < BSZ; i += 32) s += g_partial[i];
            #pragma unroll
            for (int o = 16; o; o >>= 1)
                s += __shfl_xor_sync(0xffffffffu, s, o);
            if (lane == 0) out[0] = -s / (float)BSZ;
            if (out_size >= 1 + NC * NC) {
                for (int i = lane; i < NC * NC; i += 32) out[1 + i] = sT[i];
            }
            if (lane == 0) g_count = 0;   // reset for next graph replay
        }
    }
}

extern "C" void kernel_launch(void* const* d_in, const int* in_sizes, int n_in,
                              void* d_out, int out_size) {
    const float* x = (const float*)d_in[0];
    const float* T = (const float*)d_in[1];
    const int* maskI = (const int*)d_in[2];   // bool shipped as int32
    const int* tags = (const int*)d_in[3];
    float* out = (float*)d_out;
    (void)in_sizes; (void)n_in;

    crf_fused_kernel<<<BSZ / 2, 64>>>(x, T, maskI, tags, out, out_size);
}

// round 13
// speedup vs baseline: 1.2099x; 1.2099x over previous
#include <cuda_runtime.h>
#include <cstdint>

// CRF loss: inputs [1024,512,50] f32, transitions [50,50] f32,
// masks [1024,512] int32 (bool as i32), tag_indices [1024,512] i32.
// Output: [0] = loss scalar, [1..2500] = transitions passthrough.
// Strategy: persistent blocks (6/SM pinned), LPT work queue (rows sorted by
// length descending in a pre-pass), per-block E tables built once, R11
// fwd/bwd split inner loop (warp0 alpha 0..mid, warp1 beta len-1..mid).

#define BSZ 1024
#define SLEN 512
#define NC 50
#define LOG2E 1.4426950408889634f
#define LN2   0.6931471805599453f
#define GRID_MAIN (148 * 6)

typedef unsigned long long ull;

__device__ float g_partial[BSZ];
__device__ int g_len[BSZ];
__device__ int g_order[BSZ];
__device__ unsigned int g_head = 0;
__device__ unsigned int g_count = 0;

__device__ __forceinline__ ull ffma2(ull a, ull b, ull c) {
    ull d;
    asm("fma.rn.f32x2 %0, %1, %2, %3;" : "=l"(d) : "l"(a), "l"(b), "l"(c));
    return d;
}
__device__ __forceinline__ ull fadd2(ull a, ull b) {
    ull d;
    asm("add.rn.f32x2 %0, %1, %2;" : "=l"(d) : "l"(a), "l"(b));
    return d;
}
__device__ __forceinline__ ull pack2(float lo, float hi) {
    ull d;
    asm("mov.b64 %0, {%1, %2};" : "=l"(d) : "f"(lo), "f"(hi));
    return d;
}
__device__ __forceinline__ void unpack2(float& lo, float& hi, ull v) {
    asm("mov.b64 {%0, %1}, %2;" : "=f"(lo), "=f"(hi) : "l"(v));
}
__device__ __forceinline__ float ex2f(float a) {
    float r; asm("ex2.approx.ftz.f32 %0, %1;" : "=f"(r) : "f"(a)); return r;
}
__device__ __forceinline__ float lg2f(float a) {
    float r; asm("lg2.approx.ftz.f32 %0, %1;" : "=f"(r) : "f"(a)); return r;
}

// matvec: s[c2], s[c2+1] = sum_c1 v[c1] * Eh[c1][c2 or c2+1]
__device__ __forceinline__ void matvec50(
    const float2* __restrict__ cur,
    const ull* __restrict__ E0, const ull* __restrict__ E1,
    float& s0, float& s1)
{
    const ull* pb = reinterpret_cast<const ull*>(cur);
    ull a0 = 0, a1 = 0, a2 = 0, a3 = 0;
    ull b0 = 0, b1 = 0, b2 = 0, b3 = 0;
    #pragma unroll
    for (int i = 0; i < 24; i += 4) {
        ull v0 = pb[i],     v1 = pb[i + 1];
        ull v2 = pb[i + 2], v3 = pb[i + 3];
        a0 = ffma2(v0, E0[i],     a0);
        b0 = ffma2(v0, E1[i],     b0);
        a1 = ffma2(v1, E0[i + 1], a1);
        b1 = ffma2(v1, E1[i + 1], b1);
        a2 = ffma2(v2, E0[i + 2], a2);
        b2 = ffma2(v2, E1[i + 2], b2);
        a3 = ffma2(v3, E0[i + 3], a3);
        b3 = ffma2(v3, E1[i + 3], b3);
    }
    {
        ull v = pb[24];
        a0 = ffma2(v, E0[24], a0);
        b0 = ffma2(v, E1[24], b0);
    }
    a0 = fadd2(a0, a2); a1 = fadd2(a1, a3); a0 = fadd2(a0, a1);
    b0 = fadd2(b0, b2); b1 = fadd2(b1, b3); b0 = fadd2(b0, b1);
    float u, v;
    unpack2(u, v, a0); s0 = u + v;
    unpack2(u, v, b0); s1 = u + v;
}

__device__ __forceinline__ void crf_fstep(
    float2 xc, float2& balpha, float& m, float2* __restrict__ cur,
    const ull* __restrict__ Ec0, const ull* __restrict__ Ec1,
    bool act, int lane)
{
    float p0 = ex2f(balpha.x - m);     // inactive lanes: ex2(-inf)=0, unused
    float p1 = ex2f(balpha.y - m);
    float mn = __shfl_sync(0xffffffffu, balpha.x, 0);  // stale shift, exact math
    if (act) cur[lane] = make_float2(p0, p1);
    __syncwarp();
    float s0, s1;
    matvec50(cur, Ec0, Ec1, s0, s1);
    if (act) {
        balpha.x = fmaf(xc.x, LOG2E, m + lg2f(s0));
        balpha.y = fmaf(xc.y, LOG2E, m + lg2f(s1));
    }
    m = mn;
}

__device__ __forceinline__ void crf_bstep(
    float2 xc /* x_{t+1} */, float2& bbeta, float& m, float2* __restrict__ cur,
    const ull* __restrict__ Er0, const ull* __restrict__ Er1,
    bool act, int lane)
{
    float w0 = fmaf(xc.x, LOG2E, bbeta.x);   // inactive: 0 + -inf = -inf
    float w1 = fmaf(xc.y, LOG2E, bbeta.y);
    float v0 = ex2f(w0 - m);
    float v1 = ex2f(w1 - m);
    float mn = __shfl_sync(0xffffffffu, w0, 0);
    if (act) cur[lane] = make_float2(v0, v1);
    __syncwarp();
    float s0, s1;
    matvec50(cur, Er0, Er1, s0, s1);
    if (act) {
        bbeta.x = m + lg2f(s0);
        bbeta.y = m + lg2f(s1);
    }
    m = mn;
}

// ---------- pre-pass 1: lengths + counter reset ----------
__global__ void __launch_bounds__(256) prep_len_kernel(
    const int* __restrict__ maskI)
{
    if (blockIdx.x == 0 && threadIdx.x == 0) { g_head = 0; g_count = 0; }
    int w = (blockIdx.x * blockDim.x + threadIdx.x) >> 5;   // global warp = row
    int lane = threadIdx.x & 31;
    if (w < BSZ) {
        const int4* m = reinterpret_cast<const int4*>(maskI + (size_t)w * SLEN);
        int s = 0;
        #pragma unroll
        for (int k = 0; k < 4; ++k) {
            int4 v = m[lane + 32 * k];
            s += v.x + v.y + v.z + v.w;
        }
        #pragma unroll
        for (int o = 16; o; o >>= 1)
            s += __shfl_xor_sync(0xffffffffu, s, o);
        if (lane == 0) g_len[w] = SLEN - s;   // monotone mask => [128,512]
    }
}

// ---------- pre-pass 2: counting sort by length, descending ----------
__global__ void __launch_bounds__(512) prep_sort_kernel()
{
    __shared__ int hist[SLEN + 1];
    __shared__ int start[SLEN + 1];
    int tid = threadIdx.x;
    for (int i = tid; i <= SLEN; i += 512) hist[i] = 0;
    __syncthreads();
    for (int b = tid; b < BSZ; b += 512) atomicAdd(&hist[g_len[b]], 1);
    __syncthreads();
    if (tid == 0) {
        int acc = 0;
        for (int L = SLEN; L >= 0; --L) { start[L] = acc; acc += hist[L]; }
    }
    __syncthreads();
    for (int b = tid; b < BSZ; b += 512) {
        int p = atomicAdd(&start[g_len[b]], 1);
        g_order[p] = b;
    }
}

// ---------- main: persistent blocks, LPT queue ----------
__global__ void __launch_bounds__(64, 6) crf_main_kernel(
    const float* __restrict__ x,      // [BSZ, SLEN, NC]
    const float* __restrict__ T,      // [NC, NC]
    const int* __restrict__ tags,     // [BSZ, SLEN]
    float* __restrict__ out, int out_size)
{
    __shared__ float sT[NC * NC];
    __shared__ float2 sp[2][2][26];   // [warp][buf][lane]
    __shared__ int stags[SLEN];
    __shared__ float salpha[52], sbeta[52];
    __shared__ float subs[2];
    __shared__ int srow;

    const int tid = threadIdx.x;
    const int wid = tid >> 5;         // 0 = forward, 1 = backward
    const int lane = tid & 31;
    const int c2 = 2 * lane;
    const bool act = (lane < 25);

    for (int i = tid; i < NC * NC; i += 64) sT[i] = T[i];
    __syncthreads();

    // E tables built ONCE per block (row-independent). Forward warp holds
    // E columns (c2, c2+1); backward warp holds E rows.
    ull E0[25], E1[25];
    if (wid == 0) {
        #pragma unroll
        for (int i = 0; i < 25; ++i) {
            float e00 = 0.f, e01 = 0.f, e10 = 0.f, e11 = 0.f;
            if (act) {
                e00 = ex2f(sT[(2 * i) * NC + c2] * LOG2E);
                e01 = ex2f(sT[(2 * i + 1) * NC + c2] * LOG2E);
                e10 = ex2f(sT[(2 * i) * NC + c2 + 1] * LOG2E);
                e11 = ex2f(sT[(2 * i + 1) * NC + c2 + 1] * LOG2E);
            }
            E0[i] = pack2(e00, e01);
            E1[i] = pack2(e10, e11);
        }
    } else {
        #pragma unroll
        for (int i = 0; i < 25; ++i) {
            float e00 = 0.f, e01 = 0.f, e10 = 0.f, e11 = 0.f;
            if (act) {
                e00 = ex2f(sT[c2 * NC + 2 * i] * LOG2E);
                e01 = ex2f(sT[c2 * NC + 2 * i + 1] * LOG2E);
                e10 = ex2f(sT[(c2 + 1) * NC + 2 * i] * LOG2E);
                e11 = ex2f(sT[(c2 + 1) * NC + 2 * i + 1] * LOG2E);
            }
            E0[i] = pack2(e00, e01);
            E1[i] = pack2(e10, e11);
        }
    }

    float2* buf0 = sp[wid][0];
    float2* buf1 = sp[wid][1];

    while (true) {
        if (tid == 0) {
            unsigned int idx = atomicAdd(&g_head, 1u);
            srow = (idx < BSZ) ? g_order[idx] : -1;
        }
        __syncthreads();
        const int row = srow;
        if (row < 0) break;
        const int len = g_len[row];       // in [128, 512]
        const int mid = (len - 1) >> 1;
        const float* xrow = x + (size_t)row * SLEN * NC;

        // tags -> shared (both warps)
        const int* trow = tags + (size_t)row * SLEN;
        for (int i = tid; i < len; i += 64) stags[i] = trow[i];
        __syncthreads();

        // unary + binary split across 64 threads
        float ub = 0.f;
        for (int t = tid; t < len; t += 64) {
            int tg = stags[t];
            ub += __ldg(xrow + (size_t)t * NC + tg);
            if (t > 0) ub += sT[stags[t - 1] * NC + tg];
        }
        #pragma unroll
        for (int o = 16; o; o >>= 1)
            ub += __shfl_xor_sync(0xffffffffu, ub, o);
        if (lane == 0) subs[wid] = ub;

        if (wid == 0) {
            // ---------- FORWARD: t = 1..mid ----------
            float2 x0 = act ? *reinterpret_cast<const float2*>(xrow + c2)
                            : make_float2(0.f, 0.f);
            float2 balpha = act ? make_float2(x0.x * LOG2E, x0.y * LOG2E)
                                : make_float2(-INFINITY, -INFINITY);
            float m = __shfl_sync(0xffffffffu, balpha.x, 0);

            const int lenF = mid + 1;     // >= 64
            float2 x1, x2, x3, x4;
            x1 = x2 = x3 = x4 = make_float2(0.f, 0.f);
            if (act) {
                x1 = *reinterpret_cast<const float2*>(xrow + 1 * NC + c2);
                x2 = *reinterpret_cast<const float2*>(xrow + 2 * NC + c2);
                x3 = *reinterpret_cast<const float2*>(xrow + 3 * NC + c2);
                x4 = *reinterpret_cast<const float2*>(xrow + 4 * NC + c2);
            }
            int t = 1;
            for (; t + 7 < lenF; t += 4) {
                float2 n1, n2, n3, n4;
                n1 = n2 = n3 = n4 = make_float2(0.f, 0.f);
                if (act) {
                    const float* p = xrow + (size_t)(t + 4) * NC + c2;
                    n1 = *reinterpret_cast<const float2*>(p);
                    n2 = *reinterpret_cast<const float2*>(p + NC);
                    n3 = *reinterpret_cast<const float2*>(p + 2 * NC);
                    n4 = *reinterpret_cast<const float2*>(p + 3 * NC);
                }
                crf_fstep(x1, balpha, m, buf0, E0, E1, act, lane);
                crf_fstep(x2, balpha, m, buf1, E0, E1, act, lane);
                crf_fstep(x3, balpha, m, buf0, E0, E1, act, lane);
                crf_fstep(x4, balpha, m, buf1, E0, E1, act, lane);
                x1 = n1; x2 = n2; x3 = n3; x4 = n4;
            }
            crf_fstep(x1, balpha, m, buf0, E0, E1, act, lane);
            crf_fstep(x2, balpha, m, buf1, E0, E1, act, lane);
            crf_fstep(x3, balpha, m, buf0, E0, E1, act, lane);
            crf_fstep(x4, balpha, m, buf1, E0, E1, act, lane);
            int parity = 0;
            for (int u = t + 4; u < lenF; ++u) {
                float2 xd = act ? *reinterpret_cast<const float2*>(
                                      xrow + (size_t)u * NC + c2)
                                : make_float2(0.f, 0.f);
                crf_fstep(xd, balpha, m, parity ? buf1 : buf0, E0, E1, act, lane);
                parity ^= 1;
            }
            if (act) {
                salpha[c2]     = balpha.x;
                salpha[c2 + 1] = balpha.y;
            }
        } else {
            // ---------- BACKWARD: j = 0..NB-1, consumes x[len-1-j] ----------
            float2 bbeta = act ? make_float2(0.f, 0.f)
                               : make_float2(-INFINITY, -INFINITY);
            const int NB = len - 1 - mid;  // >= 63
            const float* xbase = xrow + (size_t)(len - 1) * NC + c2;

            float2 x1, x2, x3, x4;
            x1 = x2 = x3 = x4 = make_float2(0.f, 0.f);
            if (act) {
                x1 = *reinterpret_cast<const float2*>(xbase);
                x2 = *reinterpret_cast<const float2*>(xbase - NC);
                x3 = *reinterpret_cast<const float2*>(xbase - 2 * NC);
                x4 = *reinterpret_cast<const float2*>(xbase - 3 * NC);
            }
            float m = __shfl_sync(0xffffffffu, x1.x * LOG2E, 0);

            int j = 0;
            for (; j + 7 < NB; j += 4) {
                float2 n1, n2, n3, n4;
                n1 = n2 = n3 = n4 = make_float2(0.f, 0.f);
                if (act) {
                    const float* p = xbase - (size_t)(j + 4) * NC;
                    n1 = *reinterpret_cast<const float2*>(p);
                    n2 = *reinterpret_cast<const float2*>(p - NC);
                    n3 = *reinterpret_cast<const float2*>(p - 2 * NC);
                    n4 = *reinterpret_cast<const float2*>(p - 3 * NC);
                }
                crf_bstep(x1, bbeta, m, buf0, E0, E1, act, lane);
                crf_bstep(x2, bbeta, m, buf1, E0, E1, act, lane);
                crf_bstep(x3, bbeta, m, buf0, E0, E1, act, lane);
                crf_bstep(x4, bbeta, m, buf1, E0, E1, act, lane);
                x1 = n1; x2 = n2; x3 = n3; x4 = n4;
            }
            crf_bstep(x1, bbeta, m, buf0, E0, E1, act, lane);
            crf_bstep(x2, bbeta, m, buf1, E0, E1, act, lane);
            crf_bstep(x3, bbeta, m, buf0, E0, E1, act, lane);
            crf_bstep(x4, bbeta, m, buf1, E0, E1, act, lane);
            int parity = 0;
            for (int u = j + 4; u < NB; ++u) {
                float2 xd = act ? *reinterpret_cast<const float2*>(
                                      xbase - (size_t)u * NC)
                                : make_float2(0.f, 0.f);
                crf_bstep(xd, bbeta, m, parity ? buf1 : buf0, E0, E1, act, lane);
                parity ^= 1;
            }
            if (act) {
                sbeta[c2]     = bbeta.x;
                sbeta[c2 + 1] = bbeta.y;
            }
        }
        __syncthreads();

        if (wid == 0) {
            // combine: logZ = lse_c(alpha_mid + beta_mid), log2 domain
            float g0 = act ? salpha[c2] + sbeta[c2] : -INFINITY;
            float g1 = act ? salpha[c2 + 1] + sbeta[c2 + 1] : -INFINITY;
            float mx = fmaxf(g0, g1);
            #pragma unroll
            for (int o = 16; o; o >>= 1)
                mx = fmaxf(mx, __shfl_xor_sync(0xffffffffu, mx, o));
            float es = ex2f(g0 - mx) + ex2f(g1 - mx);
            #pragma unroll
            for (int o = 16; o; o >>= 1)
                es += __shfl_xor_sync(0xffffffffu, es, o);
            float log_norm = LN2 * (mx + lg2f(es));

            unsigned int ticket = 0;
            if (lane == 0) {
                g_partial[row] = subs[0] + subs[1] - log_norm;
                __threadfence();
                ticket = atomicAdd(&g_count, 1u);
            }
            ticket = __shfl_sync(0xffffffffu, ticket, 0);
            if (ticket == BSZ - 1) {
                __threadfence();
                float s = 0.f;
                for (int i = lane; i < BSZ; i += 32) s += g_partial[i];
                #pragma unroll
                for (int o = 16; o; o >>= 1)
                    s += __shfl_xor_sync(0xffffffffu, s, o);
                if (lane == 0) out[0] = -s / (float)BSZ;
                if (out_size >= 1 + NC * NC) {
                    for (int i = lane; i < NC * NC; i += 32)
                        out[1 + i] = sT[i];
                }
            }
        }
        __syncthreads();   // protect srow/stags/subs/salpha/sbeta for next row
    }
}

extern "C" void kernel_launch(void* const* d_in, const int* in_sizes, int n_in,
                              void* d_out, int out_size) {
    const float* x = (const float*)d_in[0];
    const float* T = (const float*)d_in[1];
    const int* maskI = (const int*)d_in[2];   // bool shipped as int32
    const int* tags = (const int*)d_in[3];
    float* out = (float*)d_out;
    (void)in_sizes; (void)n_in;

    prep_len_kernel<<<128, 256>>>(maskI);
    prep_sort_kernel<<<1, 512>>>();
    crf_main_kernel<<<GRID_MAIN, 64>>>(x, T, tags, out, out_size);
}